// round 1
// baseline (speedup 1.0000x reference)
#include <cuda_runtime.h>
#include <math.h>

#define BB 16
#define EE 2048
#define FF 8192
#define QQ 20
#define DD 256
#define WDD 300
#define NRELROWS 601
#define L4D 1024
#define NWORD 50000

#define VERY_NEG -1e11f
#define VERY_SMALL 1e-10f

// ---------------- scratch (device globals; no runtime alloc) ----------------
__device__ float g_lr[NRELROWS * DD];
__device__ float g_fs[3 * NRELROWS * DD];
__device__ float g_lstmb[L4D];
__device__ float g_whhT[DD * L4D];
__device__ float g_gx[BB * QQ * L4D];
__device__ float g_qh[BB * QQ * DD];
__device__ float g_qnode[BB * DD];
__device__ float g_s0[BB * QQ * NRELROWS];
__device__ float g_Wr[BB * NRELROWS];
__device__ float g_maxb[BB];
__device__ float g_Wt[BB * FF];
__device__ float g_e2fs[BB * EE];
__device__ float g_leA[BB * EE * DD];
__device__ float g_leB[BB * EE * DD];
__device__ float g_head[BB * EE * DD];
__device__ float g_eself[BB * EE * DD];   // becomes f2e_emb in-place
__device__ float g_Asc[BB * EE * DD];
__device__ float g_pr[BB * EE];
__device__ float g_prnew[BB * EE];
__device__ float g_cnt[BB * EE];
__device__ float g_q2ev[BB * DD];
__device__ float g_biasBE[BB * DD];
__device__ float g_sred[2 * BB * DD];
__device__ float g_prsum[BB];

// ---------------- generic tiled fp32 GEMM: C = act(acc + alpha*A@W^T + bias) --
// A: M x K (row lda), optionally gathered rows via gidx. W: N x K (row ldw).
// BIASMODE: 0 none, 1 bias[n], 2 bias[(m>>11)*N + n]  (per-batch bias, E=2048)
#define BM 64
#define BN 64
#define BK 16

template <bool GATHER, bool ACCUM, bool RELU, int BIASMODE>
__global__ void __launch_bounds__(256) gemm_k(
    float* __restrict__ C, const float* __restrict__ A, int lda,
    const int* __restrict__ gidx, const float* __restrict__ W, int ldw,
    const float* __restrict__ bias, int M, int N, int K, float alpha) {
  __shared__ float As[BK][BM + 4];
  __shared__ float Ws[BK][BN + 4];
  int bm = blockIdx.y * BM, bn = blockIdx.x * BN;
  int tid = threadIdx.x;
  int tx = tid & 15, ty = tid >> 4;
  float acc[4][4] = {};
  for (int kk0 = 0; kk0 < K; kk0 += BK) {
#pragma unroll
    for (int i = 0; i < 4; i++) {
      int idx = tid + i * 256;
      int mo = idx >> 4, ko = idx & 15;
      int m = bm + mo, k = kk0 + ko;
      float v = 0.f;
      if (m < M && k < K) {
        long r = GATHER ? (long)gidx[m] : (long)m;
        v = A[r * lda + k];
      }
      As[ko][mo] = v;
    }
#pragma unroll
    for (int i = 0; i < 4; i++) {
      int idx = tid + i * 256;
      int no = idx >> 4, ko = idx & 15;
      int n = bn + no, k = kk0 + ko;
      float v = 0.f;
      if (n < N && k < K) v = W[(long)n * ldw + k];
      Ws[ko][no] = v;
    }
    __syncthreads();
#pragma unroll
    for (int k = 0; k < BK; k++) {
      float a[4], b[4];
#pragma unroll
      for (int i = 0; i < 4; i++) a[i] = As[k][ty * 4 + i];
#pragma unroll
      for (int j = 0; j < 4; j++) b[j] = Ws[k][tx * 4 + j];
#pragma unroll
      for (int i = 0; i < 4; i++)
#pragma unroll
        for (int j = 0; j < 4; j++) acc[i][j] += a[i] * b[j];
    }
    __syncthreads();
  }
#pragma unroll
  for (int i = 0; i < 4; i++) {
    int m = bm + ty * 4 + i;
    if (m >= M) continue;
#pragma unroll
    for (int j = 0; j < 4; j++) {
      int n = bn + tx * 4 + j;
      if (n >= N) continue;
      float v = alpha * acc[i][j];
      if (BIASMODE == 1) v += bias[n];
      if (BIASMODE == 2) v += bias[(m >> 11) * N + n];
      if (ACCUM) v += C[(long)m * N + n];
      if (RELU) v = fmaxf(v, 0.f);
      C[(long)m * N + n] = v;
    }
  }
}

// ---------------- small kernels ----------------
__global__ void zero_k(float* p, int n) {
  int i = blockIdx.x * 256 + threadIdx.x;
  if (i < n) p[i] = 0.f;
}
__global__ void copy_k(float* d, const float* s, int n) {
  int i = blockIdx.x * 256 + threadIdx.x;
  if (i < n) d[i] = s[i];
}
__global__ void vadd_k(float* o, const float* a, const float* b, int n) {
  int i = blockIdx.x * 256 + threadIdx.x;
  if (i < n) o[i] = a[i] + b[i];
}
__global__ void transp_k(float* o, const float* in) {  // (1024,256)->(256,1024)
  int i = blockIdx.x * 256 + threadIdx.x;
  if (i >= 1024 * 256) return;
  int g = i >> 8, k = i & 255;
  o[k * 1024 + g] = in[i];
}
__global__ void qcopy_k(float* qnode, const float* qh) {
  int b = blockIdx.x, d = threadIdx.x;
  qnode[b * DD + d] = qh[(b * QQ + QQ - 1) * DD + d];
}

__global__ void __launch_bounds__(1024) lstm_k(const float* __restrict__ gx,
                                               const float* __restrict__ whhT,
                                               float* __restrict__ qh) {
  int b = blockIdx.x, g = threadIdx.x;
  __shared__ float hs[DD], cs[DD], zs[L4D];
  if (g < DD) { hs[g] = 0.f; cs[g] = 0.f; }
  __syncthreads();
  for (int t = 0; t < QQ; t++) {
    float acc = gx[(b * QQ + t) * L4D + g];
#pragma unroll 8
    for (int k = 0; k < DD; k++) acc += hs[k] * whhT[k * L4D + g];
    zs[g] = acc;
    __syncthreads();
    if (g < DD) {
      float zi = zs[g], zf = zs[DD + g], zg = zs[2 * DD + g], zo = zs[3 * DD + g];
      float cn = (1.f / (1.f + expf(-zf))) * cs[g] +
                 (1.f / (1.f + expf(-zi))) * tanhf(zg);
      float hn = (1.f / (1.f + expf(-zo))) * tanhf(cn);
      cs[g] = cn;
      hs[g] = hn;
      qh[(b * QQ + t) * DD + g] = hn;
    }
    __syncthreads();
  }
}

__global__ void wr_k(const float* __restrict__ s0, const int* __restrict__ qt,
                     float* __restrict__ Wr) {
  int idx = blockIdx.x * 256 + threadIdx.x;
  if (idx >= BB * NRELROWS) return;
  int b = idx / NRELROWS, r = idx - b * NRELROWS;
  float raw[QQ], lg[QQ];
  float mx = -1e30f;
  for (int q = 0; q < QQ; q++) {
    float v = s0[(b * QQ + q) * NRELROWS + r];
    raw[q] = v;
    lg[q] = v + ((qt[b * QQ + q] == NWORD) ? VERY_NEG : 0.f);
    mx = fmaxf(mx, lg[q]);
  }
  float se = 0.f;
  for (int q = 0; q < QQ; q++) { lg[q] = expf(lg[q] - mx); se += lg[q]; }
  float w = 0.f;
  for (int q = 0; q < QQ; q++) w += (lg[q] / se) * raw[q];
  Wr[idx] = w;
}

__global__ void rowmax_k(const float* Wr, const int* rel, float* maxb) {
  int b = blockIdx.x;
  __shared__ float red[256];
  float mx = -1e30f;
  for (int f = threadIdx.x; f < FF; f += 256)
    mx = fmaxf(mx, Wr[b * NRELROWS + rel[b * FF + f]]);
  red[threadIdx.x] = mx;
  __syncthreads();
  for (int s = 128; s > 0; s >>= 1) {
    if (threadIdx.x < s) red[threadIdx.x] = fmaxf(red[threadIdx.x], red[threadIdx.x + s]);
    __syncthreads();
  }
  if (!threadIdx.x) maxb[b] = red[0];
}

__global__ void wtilde_k(const float* Wr, const int* rel, const int* e2f,
                         const float* maxb, float* Wt, float* e2fs) {
  int i = blockIdx.x * 256 + threadIdx.x;
  if (i >= BB * FF) return;
  int b = i >> 13;
  float wt = expf(Wr[b * NRELROWS + rel[i]] - maxb[b]);
  Wt[i] = wt;
  atomicAdd(&e2fs[b * EE + e2f[i]], wt);
}

__global__ void clamp_k(float* p, int n) {
  int i = blockIdx.x * 256 + threadIdx.x;
  if (i < n) p[i] = fmaxf(p[i], VERY_SMALL);
}

__global__ void cnt_k(float* cnt, const int* f2e) {
  int i = blockIdx.x * 256 + threadIdx.x;
  if (i >= BB * FF) return;
  atomicAdd(&cnt[(i >> 13) * EE + f2e[i]], 1.0f);
}

__global__ void fact_k(const float* __restrict__ fsl, const float* __restrict__ head,
                       const float* __restrict__ Wt, const float* __restrict__ pr,
                       const float* __restrict__ e2fs, const int* __restrict__ rel,
                       const int* __restrict__ e2f, const int* __restrict__ f2e,
                       float* __restrict__ Asc, float* __restrict__ prnew) {
  int bf = blockIdx.x;  // 0 .. B*F-1
  int b = bf >> 13;
  __shared__ float s_norm;
  __shared__ int s_esrc, s_edst, s_rel;
  if (threadIdx.x == 0) {
    int es = e2f[bf], ed = f2e[bf], r = rel[bf];
    float nrm = Wt[bf] * pr[b * EE + es] / e2fs[b * EE + es];
    s_norm = nrm; s_esrc = es; s_edst = ed; s_rel = r;
    atomicAdd(&prnew[b * EE + ed], nrm);
  }
  __syncthreads();
  int d = threadIdx.x;
  float v = fsl[s_rel * DD + d] + head[(long)(b * EE + s_esrc) * DD + d];
  v = fmaxf(v, 0.f) * s_norm;
  atomicAdd(&Asc[(long)(b * EE + s_edst) * DD + d], v);
}

__global__ void f2epre_k(float* eself, const float* cnt, const float* tb) {
  int i = blockIdx.x * 256 + threadIdx.x;
  if (i >= BB * EE * DD) return;
  eself[i] += cnt[i >> 8] * tb[i & 255];
}

__global__ void prupd_k(float* pr, const float* prnew, int n) {
  int i = blockIdx.x * 256 + threadIdx.x;
  if (i < n) pr[i] = 0.8f * prnew[i] + 0.2f * pr[i];
}

__global__ void prsum_k(const float* pr, float* prsum) {
  int b = blockIdx.x;
  __shared__ float red[256];
  float s = 0.f;
  for (int e = threadIdx.x; e < EE; e += 256) s += pr[b * EE + e];
  red[threadIdx.x] = s;
  __syncthreads();
  for (int st = 128; st > 0; st >>= 1) {
    if (threadIdx.x < st) red[threadIdx.x] += red[threadIdx.x + st];
    __syncthreads();
  }
  if (!threadIdx.x) prsum[b] = red[0];
}

__global__ void wsum_k(const float* __restrict__ pr, const float* __restrict__ le,
                       const float* __restrict__ f2e, float* __restrict__ sle,
                       float* __restrict__ sf2e) {
  int blk = blockIdx.x;
  int b = blk >> 3, ch = blk & 7;
  int d = threadIdx.x;
  float a = 0.f, c = 0.f;
  int e0 = ch * 256;
  for (int e = e0; e < e0 + 256; e++) {
    float w = pr[b * EE + e];
    a += w * le[(long)(b * EE + e) * DD + d];
    c += w * f2e[(long)(b * EE + e) * DD + d];
  }
  atomicAdd(&sle[b * DD + d], a);
  atomicAdd(&sf2e[b * DD + d], c);
}

// y[b,n] = bias[n] + sum_k x[b,k] * W[n*ldw + k]
__global__ void smallmv_k(const float* __restrict__ x, const float* __restrict__ W,
                          int ldw, const float* __restrict__ bias,
                          float* __restrict__ y, int K) {
  int b = blockIdx.x, n = threadIdx.x;
  const float* w = W + (long)n * ldw;
  const float* xb = x + b * K;
  float acc = bias ? bias[n] : 0.f;
  for (int k = 0; k < K; k++) acc += xb[k] * w[k];
  y[b * DD + n] = acc;
}

__global__ void qupd_k(const float* sle, const float* sf2e, const float* q2ev,
                       const float* prsum, const float* __restrict__ W,
                       const float* bias, float* qnode) {
  int b = blockIdx.x, n = threadIdx.x;
  const float* w = W + (long)n * 768;
  float ps = prsum[b];
  float acc = ps * bias[n];
  for (int k = 0; k < DD; k++) acc += sle[b * DD + k] * w[k];
  for (int k = 0; k < DD; k++) acc += ps * q2ev[b * DD + k] * w[DD + k];
  for (int k = 0; k < DD; k++) acc += 3.f * sf2e[b * DD + k] * w[2 * DD + k];
  qnode[b * DD + n] = acc;
}

__global__ void score_k(const float* __restrict__ le, const float* __restrict__ sw,
                        const float* __restrict__ sb, float* __restrict__ out) {
  int row = blockIdx.x * 8 + (threadIdx.x >> 5);
  int lane = threadIdx.x & 31;
  float acc = 0.f;
#pragma unroll
  for (int j = 0; j < 8; j++) {
    int k = lane + j * 32;
    acc += le[(long)row * DD + k] * sw[k];
  }
#pragma unroll
  for (int o = 16; o > 0; o >>= 1) acc += __shfl_down_sync(0xffffffffu, acc, o);
  if (!lane) out[row] = acc + sb[0];
}

// ---------------- host ----------------
extern "C" void kernel_launch(void* const* d_in, const int* in_sizes, int n_in,
                              void* d_out, int out_size) {
  const int* local_entity = (const int*)d_in[0];
  const float* q2e_adj = (const float*)d_in[1];
  const int* kb_fact_rel = (const int*)d_in[2];
  const int* query_text = (const int*)d_in[3];
  const int* e2f_ent = (const int*)d_in[5];
  const int* f2e_ent = (const int*)d_in[6];
  const float* word_emb = (const float*)d_in[7];
  const float* entity_emb = (const float*)d_in[8];
  const float* relation_emb = (const float*)d_in[9];
  const float* ent_w = (const float*)d_in[10];
  const float* ent_b = (const float*)d_in[11];
  const float* rel_w = (const float*)d_in[12];
  const float* rel_b = (const float*)d_in[13];
  const float* w_ih = (const float*)d_in[14];
  const float* w_hh = (const float*)d_in[15];
  const float* b_ih = (const float*)d_in[16];
  const float* b_hh = (const float*)d_in[17];
  const float* q2e_w = (const float*)d_in[18];
  const float* q2e_b = (const float*)d_in[19];
  const float* e2q_w = (const float*)d_in[20];
  const float* e2q_b = (const float*)d_in[21];
  const float* e2e_w = (const float*)d_in[22];
  const float* e2e_b = (const float*)d_in[23];
  const float* kb_head_w = (const float*)d_in[24];
  const float* kb_head_b = (const float*)d_in[25];
  const float* kb_tail_w = (const float*)d_in[26];
  const float* kb_tail_b = (const float*)d_in[27];
  const float* kb_self_w = (const float*)d_in[28];
  const float* kb_self_b = (const float*)d_in[29];
  const float* score_w = (const float*)d_in[30];
  const float* score_b = (const float*)d_in[31];
  float* out = (float*)d_out;
  (void)in_sizes; (void)n_in; (void)out_size;

  float *lr, *fs, *lstmb, *whhT, *gx, *qh, *qnode, *s0, *Wr, *maxb, *Wt, *e2fs;
  float *leA, *leB, *head, *eself, *Asc, *pr, *prnew, *cnt, *q2ev, *biasBE;
  float *sred, *prsum;
  cudaGetSymbolAddress((void**)&lr, g_lr);
  cudaGetSymbolAddress((void**)&fs, g_fs);
  cudaGetSymbolAddress((void**)&lstmb, g_lstmb);
  cudaGetSymbolAddress((void**)&whhT, g_whhT);
  cudaGetSymbolAddress((void**)&gx, g_gx);
  cudaGetSymbolAddress((void**)&qh, g_qh);
  cudaGetSymbolAddress((void**)&qnode, g_qnode);
  cudaGetSymbolAddress((void**)&s0, g_s0);
  cudaGetSymbolAddress((void**)&Wr, g_Wr);
  cudaGetSymbolAddress((void**)&maxb, g_maxb);
  cudaGetSymbolAddress((void**)&Wt, g_Wt);
  cudaGetSymbolAddress((void**)&e2fs, g_e2fs);
  cudaGetSymbolAddress((void**)&leA, g_leA);
  cudaGetSymbolAddress((void**)&leB, g_leB);
  cudaGetSymbolAddress((void**)&head, g_head);
  cudaGetSymbolAddress((void**)&eself, g_eself);
  cudaGetSymbolAddress((void**)&Asc, g_Asc);
  cudaGetSymbolAddress((void**)&pr, g_pr);
  cudaGetSymbolAddress((void**)&prnew, g_prnew);
  cudaGetSymbolAddress((void**)&cnt, g_cnt);
  cudaGetSymbolAddress((void**)&q2ev, g_q2ev);
  cudaGetSymbolAddress((void**)&biasBE, g_biasBE);
  cudaGetSymbolAddress((void**)&sred, g_sred);
  cudaGetSymbolAddress((void**)&prsum, g_prsum);

  const int ME = BB * EE;            // 32768
  const int MED = BB * EE * DD;      // 8388608
  dim3 gBig(4, (ME + 63) / 64);      // N=256 GEMMs on 32768 rows

  // --- prologue: relation tables, LSTM ---
  vadd_k<<<4, 256>>>(lstmb, b_ih, b_hh, L4D);
  transp_k<<<1024, 256>>>(whhT, w_hh);
  gemm_k<false, false, false, 1><<<dim3(4, (NRELROWS + 63) / 64), 256>>>(
      lr, relation_emb, 600, nullptr, rel_w, 600, rel_b, NRELROWS, 256, 600, 1.f);
  for (int l = 0; l < 3; l++)
    gemm_k<false, false, false, 1><<<dim3(4, (NRELROWS + 63) / 64), 256>>>(
        fs + l * NRELROWS * DD, lr, 256, nullptr, kb_self_w + l * 65536, 256,
        kb_self_b + l * 256, NRELROWS, 256, 256, 1.f);
  gemm_k<true, false, false, 1><<<dim3(16, 5), 256>>>(
      gx, word_emb, WDD, query_text, w_ih, WDD, lstmb, BB * QQ, L4D, WDD, 1.f);
  lstm_k<<<BB, 1024>>>(gx, whhT, qh);
  qcopy_k<<<BB, 256>>>(qnode, qh);

  // --- attention -> Wr -> W_tilde -> e2f_softmax ---
  gemm_k<false, false, false, 0><<<dim3(10, 5), 256>>>(
      s0, qh, 256, nullptr, lr, 256, nullptr, BB * QQ, NRELROWS, 256, 1.f / 16.f);
  wr_k<<<(BB * NRELROWS + 255) / 256, 256>>>(s0, query_text, Wr);
  rowmax_k<<<BB, 256>>>(Wr, kb_fact_rel, maxb);
  zero_k<<<(ME + 255) / 256, 256>>>(e2fs, ME);
  wtilde_k<<<(BB * FF) / 256, 256>>>(Wr, kb_fact_rel, e2f_ent, maxb, Wt, e2fs);
  clamp_k<<<(ME + 255) / 256, 256>>>(e2fs, ME);

  // --- entity embeddings, pagerank init, fact counts ---
  gemm_k<true, false, false, 1><<<gBig, 256>>>(
      leA, entity_emb, WDD, local_entity, ent_w, WDD, ent_b, ME, 256, WDD, 1.f);
  copy_k<<<(ME + 255) / 256, 256>>>(pr, q2e_adj, ME);
  zero_k<<<(ME + 255) / 256, 256>>>(cnt, ME);
  cnt_k<<<(BB * FF) / 256, 256>>>(cnt, f2e_ent);

  float* leCur = leA;
  float* leNxt = leB;
  for (int l = 0; l < 3; l++) {
    const float* Wh = kb_head_w + l * 65536;
    const float* Ws = kb_self_w + l * 65536;
    const float* Wtl = kb_tail_w + l * 65536;
    const float* We2e = e2e_w + l * 256 * 768;
    const float* We2q = e2q_w + l * 256 * 768;

    smallmv_k<<<BB, 256>>>(qnode, q2e_w + l * 65536, 256, q2e_b + l * 256, q2ev, 256);
    gemm_k<false, false, false, 1><<<gBig, 256>>>(
        head, leCur, 256, nullptr, Wh, 256, kb_head_b + l * 256, ME, 256, 256, 1.f);
    gemm_k<false, false, false, 1><<<gBig, 256>>>(
        eself, leCur, 256, nullptr, Ws, 256, kb_self_b + l * 256, ME, 256, 256, 1.f);
    zero_k<<<(MED + 255) / 256, 256>>>(Asc, MED);
    zero_k<<<(ME + 255) / 256, 256>>>(prnew, ME);
    fact_k<<<BB * FF, 256>>>(fs + l * NRELROWS * DD, head, Wt, pr, e2fs,
                             kb_fact_rel, e2f_ent, f2e_ent, Asc, prnew);
    f2epre_k<<<(MED + 255) / 256, 256>>>(eself, cnt, kb_tail_b + l * 256);
    gemm_k<false, true, true, 0><<<gBig, 256>>>(
        eself, Asc, 256, nullptr, Wtl, 256, nullptr, ME, 256, 256, 1.f);
    prupd_k<<<(ME + 255) / 256, 256>>>(pr, prnew, ME);
    zero_k<<<(2 * BB * DD + 255) / 256, 256>>>(sred, 2 * BB * DD);
    prsum_k<<<BB, 256>>>(pr, prsum);
    wsum_k<<<BB * 8, 256>>>(pr, leCur, eself, sred, sred + BB * DD);
    qupd_k<<<BB, 256>>>(sred, sred + BB * DD, q2ev, prsum, We2q,
                        e2q_b + l * 256, qnode);
    smallmv_k<<<BB, 256>>>(q2ev, We2e + 256, 768, e2e_b + l * 256, biasBE, 256);
    gemm_k<false, false, false, 2><<<gBig, 256>>>(
        leNxt, leCur, 256, nullptr, We2e, 768, biasBE, ME, 256, 256, 1.f);
    gemm_k<false, true, true, 0><<<gBig, 256>>>(
        leNxt, eself, 256, nullptr, We2e + 512, 768, nullptr, ME, 256, 256, 3.f);
    float* t = leCur; leCur = leNxt; leNxt = t;
  }

  score_k<<<ME / 8, 256>>>(leCur, score_w, score_b, out);
}

// round 2
// speedup vs baseline: 1.2933x; 1.2933x over previous
#include <cuda_runtime.h>
#include <math.h>
#include <stdint.h>

#define BB 16
#define EE 2048
#define FF 8192
#define QQ 20
#define DD 256
#define WDD 300
#define NRELROWS 601
#define L4D 1024
#define NWORD 50000

#define VERY_NEG -1e11f
#define VERY_SMALL 1e-10f

// ---------------- scratch (device globals; no runtime alloc) ----------------
__device__ float g_lr[NRELROWS * DD];
__device__ float g_fs[3 * NRELROWS * DD];
__device__ float g_lstmb[L4D];
__device__ float g_whhT[DD * L4D];
__device__ float g_gx[BB * QQ * L4D];
__device__ float g_qh[BB * QQ * DD];
__device__ float g_qnode[BB * DD];
__device__ float g_s0[BB * QQ * NRELROWS];
__device__ float g_Wr[BB * NRELROWS];
__device__ float g_maxb[BB];
__device__ float g_Wt[BB * FF];
__device__ float g_e2fs[BB * EE];
__device__ float g_leA[BB * EE * DD];
__device__ float g_leB[BB * EE * DD];
__device__ float g_head[BB * EE * DD];
__device__ float g_eself[BB * EE * DD];   // becomes f2e_emb in-place
__device__ float g_Asc[BB * EE * DD];
__device__ float g_pr[BB * EE];
__device__ float g_prnew[BB * EE];
__device__ float g_cnt[BB * EE];
__device__ float g_q2ev[BB * DD];
__device__ float g_biasBE[BB * DD];
__device__ float g_sred[2 * BB * DD];
__device__ float g_prsum[BB];

// ---------------- tensor-core GEMM (3xTF32 for fp32 accuracy) ----------------
// C[M,N] = act( [C +] alpha * A@W^T + bias )
// A: M x K (row stride lda), optionally row-gathered via gidx. W: N x K (row ldw).
// BIASMODE: 0 none, 1 bias[n], 2 bias[(m>>11)*N + n]
#define TBM 128
#define TBN 128
#define TBK 32
#define TLD (TBK + 4)   // padded smem row stride (floats) -> conflict-free frags

__device__ __forceinline__ void tf32split(float f, uint32_t& hi, uint32_t& lo) {
  asm("cvt.rna.tf32.f32 %0, %1;" : "=r"(hi) : "f"(f));
  float r = f - __uint_as_float(hi);
  asm("cvt.rna.tf32.f32 %0, %1;" : "=r"(lo) : "f"(r));
}

#define MMA_TF32(c, a, b)                                                  \
  asm volatile(                                                            \
      "mma.sync.aligned.m16n8k8.row.col.f32.tf32.tf32.f32 "                \
      "{%0,%1,%2,%3},{%4,%5,%6,%7},{%8,%9},{%0,%1,%2,%3};"                 \
      : "+f"((c)[0]), "+f"((c)[1]), "+f"((c)[2]), "+f"((c)[3])             \
      : "r"((a)[0]), "r"((a)[1]), "r"((a)[2]), "r"((a)[3]),                \
        "r"((b)[0]), "r"((b)[1]));

template <bool GATHER, bool ACCUM, bool RELU, int BIASMODE>
__global__ void __launch_bounds__(256) gemm_k(
    float* __restrict__ C, const float* __restrict__ A, int lda,
    const int* __restrict__ gidx, const float* __restrict__ W, int ldw,
    const float* __restrict__ bias, int M, int N, int K, float alpha) {
  __shared__ float As[TBM][TLD];
  __shared__ float Bs[TBN][TLD];
  const int bm = blockIdx.y * TBM, bn = blockIdx.x * TBN;
  const int tid = threadIdx.x;
  const int warp = tid >> 5, lane = tid & 31;
  const int g = lane >> 2, tig = lane & 3;
  const int wm = (warp >> 2) * 64, wn = (warp & 3) * 32;

  float acc[4][4][4];
#pragma unroll
  for (int i = 0; i < 4; i++)
#pragma unroll
    for (int j = 0; j < 4; j++)
#pragma unroll
      for (int c = 0; c < 4; c++) acc[i][j][c] = 0.f;

  for (int kk0 = 0; kk0 < K; kk0 += TBK) {
#pragma unroll
    for (int i = 0; i < 4; i++) {
      int idx = tid + i * 256;
      int row = idx >> 3, kq = idx & 7;
      int k = kk0 + kq * 4;
      float4 va = make_float4(0.f, 0.f, 0.f, 0.f);
      int m = bm + row;
      if (m < M) {
        long r = GATHER ? (long)gidx[m] : (long)m;
        const float* p = A + r * (long)lda + k;
        if (k + 3 < K) va = *(const float4*)p;
        else {
          if (k < K) va.x = p[0];
          if (k + 1 < K) va.y = p[1];
          if (k + 2 < K) va.z = p[2];
        }
      }
      *(float4*)&As[row][kq * 4] = va;
      float4 vb = make_float4(0.f, 0.f, 0.f, 0.f);
      int n = bn + row;
      if (n < N) {
        const float* p = W + (long)n * ldw + k;
        if (k + 3 < K) vb = *(const float4*)p;
        else {
          if (k < K) vb.x = p[0];
          if (k + 1 < K) vb.y = p[1];
          if (k + 2 < K) vb.z = p[2];
        }
      }
      *(float4*)&Bs[row][kq * 4] = vb;
    }
    __syncthreads();
#pragma unroll
    for (int ks = 0; ks < TBK; ks += 8) {
      uint32_t ahi[4][4], alo[4][4], bhi[4][2], blo[4][2];
#pragma unroll
      for (int mt = 0; mt < 4; mt++) {
        int m0 = wm + mt * 16;
        tf32split(As[m0 + g][ks + tig], ahi[mt][0], alo[mt][0]);
        tf32split(As[m0 + g + 8][ks + tig], ahi[mt][1], alo[mt][1]);
        tf32split(As[m0 + g][ks + tig + 4], ahi[mt][2], alo[mt][2]);
        tf32split(As[m0 + g + 8][ks + tig + 4], ahi[mt][3], alo[mt][3]);
      }
#pragma unroll
      for (int nt = 0; nt < 4; nt++) {
        int n0 = wn + nt * 8 + g;
        tf32split(Bs[n0][ks + tig], bhi[nt][0], blo[nt][0]);
        tf32split(Bs[n0][ks + tig + 4], bhi[nt][1], blo[nt][1]);
      }
#pragma unroll
      for (int mt = 0; mt < 4; mt++)
#pragma unroll
        for (int nt = 0; nt < 4; nt++) {
          MMA_TF32(acc[mt][nt], ahi[mt], blo[nt]);
          MMA_TF32(acc[mt][nt], alo[mt], bhi[nt]);
          MMA_TF32(acc[mt][nt], ahi[mt], bhi[nt]);
        }
    }
    __syncthreads();
  }

  // epilogue
#pragma unroll
  for (int mt = 0; mt < 4; mt++) {
#pragma unroll
    for (int nt = 0; nt < 4; nt++) {
#pragma unroll
      for (int half = 0; half < 2; half++) {
        int m = bm + wm + mt * 16 + g + half * 8;
        if (m >= M) continue;
#pragma unroll
        for (int cc = 0; cc < 2; cc++) {
          int n = bn + wn + nt * 8 + tig * 2 + cc;
          if (n >= N) continue;
          float v = alpha * acc[mt][nt][half * 2 + cc];
          if (BIASMODE == 1) v += bias[n];
          if (BIASMODE == 2) v += bias[(m >> 11) * N + n];
          long off = (long)m * N + n;
          if (ACCUM) v += C[off];
          if (RELU) v = fmaxf(v, 0.f);
          C[off] = v;
        }
      }
    }
  }
}

// ---------------- small kernels ----------------
__global__ void zero_k(float* p, int n) {
  int i = blockIdx.x * 256 + threadIdx.x;
  if (i < n) p[i] = 0.f;
}
__global__ void copy_k(float* d, const float* s, int n) {
  int i = blockIdx.x * 256 + threadIdx.x;
  if (i < n) d[i] = s[i];
}
__global__ void vadd_k(float* o, const float* a, const float* b, int n) {
  int i = blockIdx.x * 256 + threadIdx.x;
  if (i < n) o[i] = a[i] + b[i];
}
__global__ void transp_k(float* o, const float* in) {  // (1024,256)->(256,1024)
  int i = blockIdx.x * 256 + threadIdx.x;
  if (i >= 1024 * 256) return;
  int g = i >> 8, k = i & 255;
  o[k * 1024 + g] = in[i];
}
__global__ void qcopy_k(float* qnode, const float* qh) {
  int b = blockIdx.x, d = threadIdx.x;
  qnode[b * DD + d] = qh[(b * QQ + QQ - 1) * DD + d];
}

__global__ void __launch_bounds__(1024) lstm_k(const float* __restrict__ gx,
                                               const float* __restrict__ whhT,
                                               float* __restrict__ qh) {
  int b = blockIdx.x, g = threadIdx.x;
  __shared__ float hs[DD], cs[DD], zs[L4D];
  if (g < DD) { hs[g] = 0.f; cs[g] = 0.f; }
  __syncthreads();
  for (int t = 0; t < QQ; t++) {
    float acc = gx[(b * QQ + t) * L4D + g];
#pragma unroll 8
    for (int k = 0; k < DD; k++) acc += hs[k] * whhT[k * L4D + g];
    zs[g] = acc;
    __syncthreads();
    if (g < DD) {
      float zi = zs[g], zf = zs[DD + g], zg = zs[2 * DD + g], zo = zs[3 * DD + g];
      float cn = (1.f / (1.f + expf(-zf))) * cs[g] +
                 (1.f / (1.f + expf(-zi))) * tanhf(zg);
      float hn = (1.f / (1.f + expf(-zo))) * tanhf(cn);
      cs[g] = cn;
      hs[g] = hn;
      qh[(b * QQ + t) * DD + g] = hn;
    }
    __syncthreads();
  }
}

__global__ void wr_k(const float* __restrict__ s0, const int* __restrict__ qt,
                     float* __restrict__ Wr) {
  int idx = blockIdx.x * 256 + threadIdx.x;
  if (idx >= BB * NRELROWS) return;
  int b = idx / NRELROWS, r = idx - b * NRELROWS;
  float raw[QQ], lg[QQ];
  float mx = -1e30f;
  for (int q = 0; q < QQ; q++) {
    float v = s0[(b * QQ + q) * NRELROWS + r];
    raw[q] = v;
    lg[q] = v + ((qt[b * QQ + q] == NWORD) ? VERY_NEG : 0.f);
    mx = fmaxf(mx, lg[q]);
  }
  float se = 0.f;
  for (int q = 0; q < QQ; q++) { lg[q] = expf(lg[q] - mx); se += lg[q]; }
  float w = 0.f;
  for (int q = 0; q < QQ; q++) w += (lg[q] / se) * raw[q];
  Wr[idx] = w;
}

__global__ void rowmax_k(const float* Wr, const int* rel, float* maxb) {
  int b = blockIdx.x;
  __shared__ float red[256];
  float mx = -1e30f;
  for (int f = threadIdx.x; f < FF; f += 256)
    mx = fmaxf(mx, Wr[b * NRELROWS + rel[b * FF + f]]);
  red[threadIdx.x] = mx;
  __syncthreads();
  for (int s = 128; s > 0; s >>= 1) {
    if (threadIdx.x < s) red[threadIdx.x] = fmaxf(red[threadIdx.x], red[threadIdx.x + s]);
    __syncthreads();
  }
  if (!threadIdx.x) maxb[b] = red[0];
}

__global__ void wtilde_k(const float* Wr, const int* rel, const int* e2f,
                         const float* maxb, float* Wt, float* e2fs) {
  int i = blockIdx.x * 256 + threadIdx.x;
  if (i >= BB * FF) return;
  int b = i >> 13;
  float wt = expf(Wr[b * NRELROWS + rel[i]] - maxb[b]);
  Wt[i] = wt;
  atomicAdd(&e2fs[b * EE + e2f[i]], wt);
}

__global__ void clamp_k(float* p, int n) {
  int i = blockIdx.x * 256 + threadIdx.x;
  if (i < n) p[i] = fmaxf(p[i], VERY_SMALL);
}

__global__ void cnt_k(float* cnt, const int* f2e) {
  int i = blockIdx.x * 256 + threadIdx.x;
  if (i >= BB * FF) return;
  atomicAdd(&cnt[(i >> 13) * EE + f2e[i]], 1.0f);
}

__global__ void fact_k(const float* __restrict__ fsl, const float* __restrict__ head,
                       const float* __restrict__ Wt, const float* __restrict__ pr,
                       const float* __restrict__ e2fs, const int* __restrict__ rel,
                       const int* __restrict__ e2f, const int* __restrict__ f2e,
                       float* __restrict__ Asc, float* __restrict__ prnew) {
  int bf = blockIdx.x;  // 0 .. B*F-1
  int b = bf >> 13;
  __shared__ float s_norm;
  __shared__ int s_esrc, s_edst, s_rel;
  if (threadIdx.x == 0) {
    int es = e2f[bf], ed = f2e[bf], r = rel[bf];
    float nrm = Wt[bf] * pr[b * EE + es] / e2fs[b * EE + es];
    s_norm = nrm; s_esrc = es; s_edst = ed; s_rel = r;
    atomicAdd(&prnew[b * EE + ed], nrm);
  }
  __syncthreads();
  int d = threadIdx.x;
  float v = fsl[s_rel * DD + d] + head[(long)(b * EE + s_esrc) * DD + d];
  v = fmaxf(v, 0.f) * s_norm;
  atomicAdd(&Asc[(long)(b * EE + s_edst) * DD + d], v);
}

__global__ void f2epre_k(float* eself, const float* cnt, const float* tb) {
  int i = blockIdx.x * 256 + threadIdx.x;
  if (i >= BB * EE * DD) return;
  eself[i] += cnt[i >> 8] * tb[i & 255];
}

__global__ void prupd_k(float* pr, const float* prnew, int n) {
  int i = blockIdx.x * 256 + threadIdx.x;
  if (i < n) pr[i] = 0.8f * prnew[i] + 0.2f * pr[i];
}

__global__ void prsum_k(const float* pr, float* prsum) {
  int b = blockIdx.x;
  __shared__ float red[256];
  float s = 0.f;
  for (int e = threadIdx.x; e < EE; e += 256) s += pr[b * EE + e];
  red[threadIdx.x] = s;
  __syncthreads();
  for (int st = 128; st > 0; st >>= 1) {
    if (threadIdx.x < st) red[threadIdx.x] += red[threadIdx.x + st];
    __syncthreads();
  }
  if (!threadIdx.x) prsum[b] = red[0];
}

__global__ void wsum_k(const float* __restrict__ pr, const float* __restrict__ le,
                       const float* __restrict__ f2e, float* __restrict__ sle,
                       float* __restrict__ sf2e) {
  int blk = blockIdx.x;
  int b = blk >> 3, ch = blk & 7;
  int d = threadIdx.x;
  float a = 0.f, c = 0.f;
  int e0 = ch * 256;
  for (int e = e0; e < e0 + 256; e++) {
    float w = pr[b * EE + e];
    a += w * le[(long)(b * EE + e) * DD + d];
    c += w * f2e[(long)(b * EE + e) * DD + d];
  }
  atomicAdd(&sle[b * DD + d], a);
  atomicAdd(&sf2e[b * DD + d], c);
}

// y[b,n] = bias[n] + sum_k x[b,k] * W[n*ldw + k]
__global__ void smallmv_k(const float* __restrict__ x, const float* __restrict__ W,
                          int ldw, const float* __restrict__ bias,
                          float* __restrict__ y, int K) {
  int b = blockIdx.x, n = threadIdx.x;
  const float* w = W + (long)n * ldw;
  const float* xb = x + b * K;
  float acc = bias ? bias[n] : 0.f;
  for (int k = 0; k < K; k++) acc += xb[k] * w[k];
  y[b * DD + n] = acc;
}

__global__ void qupd_k(const float* sle, const float* sf2e, const float* q2ev,
                       const float* prsum, const float* __restrict__ W,
                       const float* bias, float* qnode) {
  int b = blockIdx.x, n = threadIdx.x;
  const float* w = W + (long)n * 768;
  float ps = prsum[b];
  float acc = ps * bias[n];
  for (int k = 0; k < DD; k++) acc += sle[b * DD + k] * w[k];
  for (int k = 0; k < DD; k++) acc += ps * q2ev[b * DD + k] * w[DD + k];
  for (int k = 0; k < DD; k++) acc += 3.f * sf2e[b * DD + k] * w[2 * DD + k];
  qnode[b * DD + n] = acc;
}

__global__ void score_k(const float* __restrict__ le, const float* __restrict__ sw,
                        const float* __restrict__ sb, float* __restrict__ out) {
  int row = blockIdx.x * 8 + (threadIdx.x >> 5);
  int lane = threadIdx.x & 31;
  float acc = 0.f;
#pragma unroll
  for (int j = 0; j < 8; j++) {
    int k = lane + j * 32;
    acc += le[(long)row * DD + k] * sw[k];
  }
#pragma unroll
  for (int o = 16; o > 0; o >>= 1) acc += __shfl_down_sync(0xffffffffu, acc, o);
  if (!lane) out[row] = acc + sb[0];
}

// ---------------- host ----------------
extern "C" void kernel_launch(void* const* d_in, const int* in_sizes, int n_in,
                              void* d_out, int out_size) {
  const int* local_entity = (const int*)d_in[0];
  const float* q2e_adj = (const float*)d_in[1];
  const int* kb_fact_rel = (const int*)d_in[2];
  const int* query_text = (const int*)d_in[3];
  const int* e2f_ent = (const int*)d_in[5];
  const int* f2e_ent = (const int*)d_in[6];
  const float* word_emb = (const float*)d_in[7];
  const float* entity_emb = (const float*)d_in[8];
  const float* relation_emb = (const float*)d_in[9];
  const float* ent_w = (const float*)d_in[10];
  const float* ent_b = (const float*)d_in[11];
  const float* rel_w = (const float*)d_in[12];
  const float* rel_b = (const float*)d_in[13];
  const float* w_ih = (const float*)d_in[14];
  const float* w_hh = (const float*)d_in[15];
  const float* b_ih = (const float*)d_in[16];
  const float* b_hh = (const float*)d_in[17];
  const float* q2e_w = (const float*)d_in[18];
  const float* q2e_b = (const float*)d_in[19];
  const float* e2q_w = (const float*)d_in[20];
  const float* e2q_b = (const float*)d_in[21];
  const float* e2e_w = (const float*)d_in[22];
  const float* e2e_b = (const float*)d_in[23];
  const float* kb_head_w = (const float*)d_in[24];
  const float* kb_head_b = (const float*)d_in[25];
  const float* kb_tail_w = (const float*)d_in[26];
  const float* kb_tail_b = (const float*)d_in[27];
  const float* kb_self_w = (const float*)d_in[28];
  const float* kb_self_b = (const float*)d_in[29];
  const float* score_w = (const float*)d_in[30];
  const float* score_b = (const float*)d_in[31];
  float* out = (float*)d_out;
  (void)in_sizes; (void)n_in; (void)out_size;

  float *lr, *fs, *lstmb, *whhT, *gx, *qh, *qnode, *s0, *Wr, *maxb, *Wt, *e2fs;
  float *leA, *leB, *head, *eself, *Asc, *pr, *prnew, *cnt, *q2ev, *biasBE;
  float *sred, *prsum;
  cudaGetSymbolAddress((void**)&lr, g_lr);
  cudaGetSymbolAddress((void**)&fs, g_fs);
  cudaGetSymbolAddress((void**)&lstmb, g_lstmb);
  cudaGetSymbolAddress((void**)&whhT, g_whhT);
  cudaGetSymbolAddress((void**)&gx, g_gx);
  cudaGetSymbolAddress((void**)&qh, g_qh);
  cudaGetSymbolAddress((void**)&qnode, g_qnode);
  cudaGetSymbolAddress((void**)&s0, g_s0);
  cudaGetSymbolAddress((void**)&Wr, g_Wr);
  cudaGetSymbolAddress((void**)&maxb, g_maxb);
  cudaGetSymbolAddress((void**)&Wt, g_Wt);
  cudaGetSymbolAddress((void**)&e2fs, g_e2fs);
  cudaGetSymbolAddress((void**)&leA, g_leA);
  cudaGetSymbolAddress((void**)&leB, g_leB);
  cudaGetSymbolAddress((void**)&head, g_head);
  cudaGetSymbolAddress((void**)&eself, g_eself);
  cudaGetSymbolAddress((void**)&Asc, g_Asc);
  cudaGetSymbolAddress((void**)&pr, g_pr);
  cudaGetSymbolAddress((void**)&prnew, g_prnew);
  cudaGetSymbolAddress((void**)&cnt, g_cnt);
  cudaGetSymbolAddress((void**)&q2ev, g_q2ev);
  cudaGetSymbolAddress((void**)&biasBE, g_biasBE);
  cudaGetSymbolAddress((void**)&sred, g_sred);
  cudaGetSymbolAddress((void**)&prsum, g_prsum);

  const int ME = BB * EE;            // 32768
  const int MED = BB * EE * DD;      // 8388608
  dim3 gBig(2, ME / TBM);            // N=256 GEMMs on 32768 rows
  dim3 gRel(2, (NRELROWS + TBM - 1) / TBM);

  // --- prologue: relation tables, LSTM ---
  vadd_k<<<4, 256>>>(lstmb, b_ih, b_hh, L4D);
  transp_k<<<1024, 256>>>(whhT, w_hh);
  gemm_k<false, false, false, 1><<<gRel, 256>>>(
      lr, relation_emb, 600, nullptr, rel_w, 600, rel_b, NRELROWS, 256, 600, 1.f);
  for (int l = 0; l < 3; l++)
    gemm_k<false, false, false, 1><<<gRel, 256>>>(
        fs + l * NRELROWS * DD, lr, 256, nullptr, kb_self_w + l * 65536, 256,
        kb_self_b + l * 256, NRELROWS, 256, 256, 1.f);
  gemm_k<true, false, false, 1><<<dim3(8, 3), 256>>>(
      gx, word_emb, WDD, query_text, w_ih, WDD, lstmb, BB * QQ, L4D, WDD, 1.f);
  lstm_k<<<BB, 1024>>>(gx, whhT, qh);
  qcopy_k<<<BB, 256>>>(qnode, qh);

  // --- attention -> Wr -> W_tilde -> e2f_softmax ---
  gemm_k<false, false, false, 0><<<dim3(5, 3), 256>>>(
      s0, qh, 256, nullptr, lr, 256, nullptr, BB * QQ, NRELROWS, 256, 1.f / 16.f);
  wr_k<<<(BB * NRELROWS + 255) / 256, 256>>>(s0, query_text, Wr);
  rowmax_k<<<BB, 256>>>(Wr, kb_fact_rel, maxb);
  zero_k<<<(ME + 255) / 256, 256>>>(e2fs, ME);
  wtilde_k<<<(BB * FF) / 256, 256>>>(Wr, kb_fact_rel, e2f_ent, maxb, Wt, e2fs);
  clamp_k<<<(ME + 255) / 256, 256>>>(e2fs, ME);

  // --- entity embeddings, pagerank init, fact counts ---
  gemm_k<true, false, false, 1><<<gBig, 256>>>(
      leA, entity_emb, WDD, local_entity, ent_w, WDD, ent_b, ME, 256, WDD, 1.f);
  copy_k<<<(ME + 255) / 256, 256>>>(pr, q2e_adj, ME);
  zero_k<<<(ME + 255) / 256, 256>>>(cnt, ME);
  cnt_k<<<(BB * FF) / 256, 256>>>(cnt, f2e_ent);

  float* leCur = leA;
  float* leNxt = leB;
  for (int l = 0; l < 3; l++) {
    const float* Wh = kb_head_w + l * 65536;
    const float* Ws = kb_self_w + l * 65536;
    const float* Wtl = kb_tail_w + l * 65536;
    const float* We2e = e2e_w + l * 256 * 768;
    const float* We2q = e2q_w + l * 256 * 768;

    smallmv_k<<<BB, 256>>>(qnode, q2e_w + l * 65536, 256, q2e_b + l * 256, q2ev, 256);
    gemm_k<false, false, false, 1><<<gBig, 256>>>(
        head, leCur, 256, nullptr, Wh, 256, kb_head_b + l * 256, ME, 256, 256, 1.f);
    gemm_k<false, false, false, 1><<<gBig, 256>>>(
        eself, leCur, 256, nullptr, Ws, 256, kb_self_b + l * 256, ME, 256, 256, 1.f);
    zero_k<<<(MED + 255) / 256, 256>>>(Asc, MED);
    zero_k<<<(ME + 255) / 256, 256>>>(prnew, ME);
    fact_k<<<BB * FF, 256>>>(fs + l * NRELROWS * DD, head, Wt, pr, e2fs,
                             kb_fact_rel, e2f_ent, f2e_ent, Asc, prnew);
    f2epre_k<<<(MED + 255) / 256, 256>>>(eself, cnt, kb_tail_b + l * 256);
    gemm_k<false, true, true, 0><<<gBig, 256>>>(
        eself, Asc, 256, nullptr, Wtl, 256, nullptr, ME, 256, 256, 1.f);
    prupd_k<<<(ME + 255) / 256, 256>>>(pr, prnew, ME);
    zero_k<<<(2 * BB * DD + 255) / 256, 256>>>(sred, 2 * BB * DD);
    prsum_k<<<BB, 256>>>(pr, prsum);
    wsum_k<<<BB * 8, 256>>>(pr, leCur, eself, sred, sred + BB * DD);
    qupd_k<<<BB, 256>>>(sred, sred + BB * DD, q2ev, prsum, We2q,
                        e2q_b + l * 256, qnode);
    smallmv_k<<<BB, 256>>>(q2ev, We2e + 256, 768, e2e_b + l * 256, biasBE, 256);
    gemm_k<false, false, false, 2><<<gBig, 256>>>(
        leNxt, leCur, 256, nullptr, We2e, 768, biasBE, ME, 256, 256, 1.f);
    gemm_k<false, true, true, 0><<<gBig, 256>>>(
        leNxt, eself, 256, nullptr, We2e + 512, 768, nullptr, ME, 256, 256, 3.f);
    float* t = leCur; leCur = leNxt; leNxt = t;
  }

  score_k<<<ME / 8, 256>>>(leCur, score_w, score_b, out);
}